// round 2
// baseline (speedup 1.0000x reference)
#include <cuda_runtime.h>
#include <math.h>

#define B_   16
#define C_   512
#define L_   1024
#define LP_  1022
#define H_   8
#define DH_  64

// Scratch for Q/K/V conv outputs: [3][B][C][LP], ~100MB total (global, no alloc)
__device__ float g_qkv[3][B_ * C_ * LP_];

// ---------------------------------------------------------------------------
// Fused QKV conv1d: y[which][b][oc][l] = sum_{ic,k} w[oc][ic][k] * x[b][ic][l+k] + bias
// Implicit GEMM, 64x64 output tile per CTA, 4x4 per thread, ic-chunks of 16.
// ---------------------------------------------------------------------------
__global__ __launch_bounds__(256) void conv_kernel(
    const float* __restrict__ x,
    const float* __restrict__ w0, const float* __restrict__ b0,
    const float* __restrict__ w1, const float* __restrict__ b1,
    const float* __restrict__ w2, const float* __restrict__ b2)
{
    __shared__ float Xs[16][72];   // 16 in-channels x (64+2) positions (+pad)
    __shared__ float Ws[64][48];   // 64 out-channels x (16 ic * 3 k)

    const int b  = blockIdx.z;
    const int ot = blockIdx.y;     // 0..23 over 1536 output channels
    const int lt = blockIdx.x;     // 0..15 over 1022 positions
    const int l0 = lt * 64;
    const int t  = threadIdx.x;
    const int to = t >> 4;         // 0..15 -> 4 output rows each
    const int tl = t & 15;         // 0..15 -> 4 output cols each

    const int og_base = ot * 64;
    const int which   = og_base >> 9;     // 0:q 1:k 2:v (64 | 512, tile never straddles)
    const int oc_base = og_base & 511;
    const float* wp = (which == 0) ? w0 : (which == 1) ? w1 : w2;
    const float* bp = (which == 0) ? b0 : (which == 1) ? b1 : b2;

    float acc[4][4];
#pragma unroll
    for (int i = 0; i < 4; i++)
#pragma unroll
        for (int j = 0; j < 4; j++) acc[i][j] = 0.f;

    for (int ic0 = 0; ic0 < C_; ic0 += 16) {
        // load weights: 64 rows x 48 contiguous floats (ic-chunk x 3 taps)
        for (int e = t; e < 64 * 48; e += 256) {
            int o = e / 48, j = e % 48;
            Ws[o][j] = wp[(oc_base + o) * (C_ * 3) + ic0 * 3 + j];
        }
        // load x slice: 16 rows x 66 positions
        for (int e = t; e < 16 * 66; e += 256) {
            int ic = e / 66, l = e % 66;
            int lg = l0 + l;
            Xs[ic][l] = (lg < L_) ? x[((b * C_) + (ic0 + ic)) * L_ + lg] : 0.f;
        }
        __syncthreads();

#pragma unroll
        for (int ic = 0; ic < 16; ic++) {
#pragma unroll
            for (int kk = 0; kk < 3; kk++) {
                float wv[4], xv[4];
#pragma unroll
                for (int i = 0; i < 4; i++) wv[i] = Ws[to * 4 + i][ic * 3 + kk];
#pragma unroll
                for (int j = 0; j < 4; j++) xv[j] = Xs[ic][tl * 4 + j + kk];
#pragma unroll
                for (int i = 0; i < 4; i++)
#pragma unroll
                    for (int j = 0; j < 4; j++)
                        acc[i][j] = fmaf(wv[i], xv[j], acc[i][j]);
            }
        }
        __syncthreads();
    }

#pragma unroll
    for (int i = 0; i < 4; i++) {
        const int oc = oc_base + to * 4 + i;
        const float bias = bp[oc];
#pragma unroll
        for (int j = 0; j < 4; j++) {
            const int l = l0 + tl * 4 + j;
            if (l < LP_)
                g_qkv[which][((b * C_) + oc) * LP_ + l] = acc[i][j] + bias;
        }
    }
}

// ---------------------------------------------------------------------------
// Flash attention: one CTA per (b, h, q-tile of 64). Online softmax over
// 16 k-tiles of 64. scale = 1/sqrt(512).
// Channel-major layouts: Q/K/V rows are [d][l], contiguous in l.
// ---------------------------------------------------------------------------
#define QKV_STRIDE 68
#define P_STRIDE   65

__global__ __launch_bounds__(256) void attn_kernel(float* __restrict__ out)
{
    extern __shared__ float sm[];
    float* Qs   = sm;                        // [64][68]  (d-major)
    float* Ks   = Qs + 64 * QKV_STRIDE;      // [64][68]
    float* Vs   = Ks + 64 * QKV_STRIDE;      // [64][68]
    float* Ps   = Vs + 64 * QKV_STRIDE;      // [64][65]  (q-major)
    float* mrow = Ps + 64 * P_STRIDE;        // [64]
    float* lrow = mrow + 64;                 // [64]
    float* arow = lrow + 64;                 // [64]

    const int b  = blockIdx.z;
    const int h  = blockIdx.y;
    const int qt = blockIdx.x;
    const int q0 = qt * 64;
    const int t  = threadIdx.x;

    const float* Qg = g_qkv[0] + ((size_t)(b * C_) + h * DH_) * LP_;
    const float* Kg = g_qkv[1] + ((size_t)(b * C_) + h * DH_) * LP_;
    const float* Vg = g_qkv[2] + ((size_t)(b * C_) + h * DH_) * LP_;

    // load Q tile [64 d][64 q]
    for (int e = t; e < 4096; e += 256) {
        int d = e >> 6, q = e & 63;
        int qg = q0 + q;
        Qs[d * QKV_STRIDE + q] = (qg < LP_) ? Qg[d * LP_ + qg] : 0.f;
    }
    if (t < 64) { mrow[t] = -1e30f; lrow[t] = 0.f; }

    const int tq = t >> 4, tk = t & 15;      // S-GEMM: 4 q-rows x 4 k-cols per thread
    const float scale = 0.04419417382415922f;  // 1/sqrt(512)

    float o_acc[4][4];
#pragma unroll
    for (int i = 0; i < 4; i++)
#pragma unroll
        for (int j = 0; j < 4; j++) o_acc[i][j] = 0.f;

    for (int kt = 0; kt < 16; kt++) {
        const int k0 = kt * 64;
        __syncthreads();   // protect Ks/Vs/Ps from previous iteration readers

        for (int e = t; e < 4096; e += 256) {
            int d = e >> 6, kk = e & 63;
            int kg = k0 + kk;
            float kvld = (kg < LP_) ? Kg[d * LP_ + kg] : 0.f;
            float vvld = (kg < LP_) ? Vg[d * LP_ + kg] : 0.f;
            Ks[d * QKV_STRIDE + kk] = kvld;
            Vs[d * QKV_STRIDE + kk] = vvld;
        }
        __syncthreads();

        // S = (Q^T K) * scale
        float s[4][4];
#pragma unroll
        for (int i = 0; i < 4; i++)
#pragma unroll
            for (int j = 0; j < 4; j++) s[i][j] = 0.f;

        for (int d = 0; d < 64; d++) {
            float qv[4], kv[4];
#pragma unroll
            for (int i = 0; i < 4; i++) qv[i] = Qs[d * QKV_STRIDE + tq * 4 + i];
#pragma unroll
            for (int j = 0; j < 4; j++) kv[j] = Ks[d * QKV_STRIDE + tk * 4 + j];
#pragma unroll
            for (int i = 0; i < 4; i++)
#pragma unroll
                for (int j = 0; j < 4; j++)
                    s[i][j] = fmaf(qv[i], kv[j], s[i][j]);
        }
#pragma unroll
        for (int i = 0; i < 4; i++)
#pragma unroll
            for (int j = 0; j < 4; j++) {
                s[i][j] *= scale;
                if (k0 + tk * 4 + j >= LP_) s[i][j] = -1e30f;
            }

        // online softmax update per q-row; 16 lanes (tk) cooperate per row
#pragma unroll
        for (int i = 0; i < 4; i++) {
            const int q = tq * 4 + i;
            float rm = fmaxf(fmaxf(s[i][0], s[i][1]), fmaxf(s[i][2], s[i][3]));
#pragma unroll
            for (int off = 8; off > 0; off >>= 1)
                rm = fmaxf(rm, __shfl_xor_sync(0xffffffffu, rm, off, 16));
            const float mold = mrow[q];
            const float mnew = fmaxf(mold, rm);
            float ps = 0.f;
#pragma unroll
            for (int j = 0; j < 4; j++) {
                s[i][j] = __expf(s[i][j] - mnew);
                ps += s[i][j];
            }
#pragma unroll
            for (int off = 8; off > 0; off >>= 1)
                ps += __shfl_xor_sync(0xffffffffu, ps, off, 16);
            if (tk == 0) {
                const float al = __expf(mold - mnew);
                arow[q] = al;
                lrow[q] = lrow[q] * al + ps;
                mrow[q] = mnew;
            }
#pragma unroll
            for (int j = 0; j < 4; j++)
                Ps[q * P_STRIDE + tk * 4 + j] = s[i][j];
        }
        __syncthreads();

        // O = O*alpha + V @ P^T   (td = d-rows, tq2 = q-cols)
        const int td = tq, tq2 = tk;
        float av[4];
#pragma unroll
        for (int j = 0; j < 4; j++) av[j] = arow[tq2 * 4 + j];
#pragma unroll
        for (int i = 0; i < 4; i++)
#pragma unroll
            for (int j = 0; j < 4; j++) o_acc[i][j] *= av[j];

        for (int kk = 0; kk < 64; kk++) {
            float vv[4], pv[4];
#pragma unroll
            for (int i = 0; i < 4; i++) vv[i] = Vs[(td * 4 + i) * QKV_STRIDE + kk];
#pragma unroll
            for (int j = 0; j < 4; j++) pv[j] = Ps[(tq2 * 4 + j) * P_STRIDE + kk];
#pragma unroll
            for (int i = 0; i < 4; i++)
#pragma unroll
                for (int j = 0; j < 4; j++)
                    o_acc[i][j] = fmaf(vv[i], pv[j], o_acc[i][j]);
        }
    }

    // epilogue: normalize by l, write out[b, h*64+d, q]
    const int td = tq, tq2 = tk;
#pragma unroll
    for (int j = 0; j < 4; j++) {
        const int q = q0 + tq2 * 4 + j;
        if (q >= LP_) continue;
        const float inv = 1.f / lrow[tq2 * 4 + j];
#pragma unroll
        for (int i = 0; i < 4; i++) {
            const int d = td * 4 + i;
            out[((size_t)(b * C_) + h * DH_ + d) * LP_ + q] = o_acc[i][j] * inv;
        }
    }
}

// ---------------------------------------------------------------------------
extern "C" void kernel_launch(void* const* d_in, const int* in_sizes, int n_in,
                              void* d_out, int out_size)
{
    const float* x  = (const float*)d_in[0];
    const float* w0 = (const float*)d_in[1];
    const float* b0 = (const float*)d_in[2];
    const float* w1 = (const float*)d_in[3];
    const float* b1 = (const float*)d_in[4];
    const float* w2 = (const float*)d_in[5];
    const float* b2 = (const float*)d_in[6];
    float* out = (float*)d_out;

    // Fused QKV conv: grid (l-tiles, o-tiles over 1536, batch)
    conv_kernel<<<dim3(16, 24, 16), 256>>>(x, w0, b0, w1, b1, w2, b2);

    // Flash attention: grid (q-tiles, heads, batch)
    const size_t smem = (size_t)(3 * 64 * QKV_STRIDE + 64 * P_STRIDE + 3 * 64) * sizeof(float);
    cudaFuncSetAttribute(attn_kernel, cudaFuncAttributeMaxDynamicSharedMemorySize, (int)smem);
    attn_kernel<<<dim3(16, H_, B_), 256, smem>>>(out);
}